// round 5
// baseline (speedup 1.0000x reference)
#include <cuda_runtime.h>
#include <math.h>
#include <stdint.h>

#define BB   16384

// ---------------- scratch (device globals; no allocs allowed) ----------------
__device__ float g_content0[BB * 128];
__device__ float g_c0ez[BB * 128];
__device__ float g_mempre[(size_t)BB * 4096];
__device__ float g_sig[BB * 192];
__device__ float g_zt[BB * 64];
__device__ float g_erase[BB * 64];
__device__ float g_ztwza[BB * 64];
__device__ float g_ww[BB * 64];

__device__ __forceinline__ float sigmoidf_(float x) { return 1.0f / (1.0f + __expf(-x)); }

__device__ __forceinline__ uint32_t smem_u32(const void* p) {
    uint32_t a;
    asm("{ .reg .u64 t; cvta.to.shared.u64 t, %1; cvt.u32.u64 %0, t; }" : "=r"(a) : "l"(p));
    return a;
}
__device__ __forceinline__ void ldsm4(uint32_t* d, uint32_t addr) {
    asm volatile("ldmatrix.sync.aligned.m8n8.x4.shared.b16 {%0,%1,%2,%3}, [%4];"
        : "=r"(d[0]), "=r"(d[1]), "=r"(d[2]), "=r"(d[3]) : "r"(addr));
}
__device__ __forceinline__ void mma8(float* c, const uint32_t* a, uint32_t b0, uint32_t b1) {
    asm volatile("mma.sync.aligned.m16n8k8.row.col.f32.tf32.tf32.f32 "
        "{%0,%1,%2,%3}, {%4,%5,%6,%7}, {%8,%9}, {%0,%1,%2,%3};"
        : "+f"(c[0]), "+f"(c[1]), "+f"(c[2]), "+f"(c[3])
        : "r"(a[0]), "r"(a[1]), "r"(a[2]), "r"(a[3]), "r"(b0), "r"(b1));
}
__device__ __forceinline__ void cp16(uint32_t dst, const void* src) {
    asm volatile("cp.async.cg.shared.global [%0], [%1], 16;" :: "r"(dst), "l"(src));
}
__device__ __forceinline__ void cp4(uint32_t dst, const void* src) {
    asm volatile("cp.async.ca.shared.global [%0], [%1], 4;" :: "r"(dst), "l"(src));
}
__device__ __forceinline__ void cp_commit() {
    asm volatile("cp.async.commit_group;" ::: "memory");
}
template <int N>
__device__ __forceinline__ void cp_wait() {
    asm volatile("cp.async.wait_group %0;" :: "n"(N) : "memory");
}

// ====================== tf32 mma.sync GEMM, cp.async 4-stage pipeline ======================
// C[16384 x 64-col-group] = A[16384 x KC] @ W[KC x .]; BM=128, NB=64, BK=32; 8 warps (2M x 4N).
enum { MM_C0 = 0, MM_GATE = 1, MM_SIG = 2 };

template <int MODE, int KC, int LDA>
__global__ void __launch_bounds__(256, 2) mma_k(
    const float* __restrict__ Aarg,
    const float* __restrict__ W0, const float* __restrict__ W1, const float* __restrict__ W2,
    const float* __restrict__ b0, const float* __restrict__ b1, const float* __restrict__ b2,
    const float* __restrict__ X)
{
    constexpr int NB = 64, BK = 32;
    constexpr int NCH = KC / BK;
    constexpr int STAGES = 4;
    constexpr int ABUF = 128 * BK * 4;      // 16 KB
    constexpr int BBUF = NB * BK * 4;       //  8 KB
    constexpr int STG  = ABUF + BBUF;
    constexpr int WNP  = NB + 4;

    extern __shared__ char smem[];
    const int tid  = threadIdx.x;
    const int lane = tid & 31;
    const int wid  = tid >> 5;
    const int wm   = wid & 1;
    const int wn   = wid >> 1;
    const int n0   = blockIdx.x * NB;
    const int m0   = blockIdx.y * 128;

    const float* A = (MODE == MM_C0) ? Aarg : (MODE == MM_GATE) ? g_content0 : g_mempre;
    const float* W;
    const float* bias;
    if constexpr (MODE == MM_SIG) {
        W    = (blockIdx.x == 0) ? W0 : (blockIdx.x == 1) ? W1 : W2;
        bias = (blockIdx.x == 0) ? b0 : (blockIdx.x == 1) ? b1 : b2;
    } else { W = W0; bias = b0; }

    uint32_t sbase = smem_u32(smem);

    auto issue = [&](int c) {
        const int st = c & (STAGES - 1);
        const uint32_t ab = sbase + st * STG;
        const uint32_t bb = ab + ABUF;
        const int kt = c * BK;
#pragma unroll
        for (int t = 0; t < 4; t++) {                 // A: 128 rows x 32 k
            int v = tid + t * 256;
            int kq = v & 7, r = v >> 3;
            cp16(ab + (kq * 128 + r) * 16, &A[(size_t)(m0 + r) * LDA + kt + kq * 4]);
        }
#pragma unroll
        for (int t = 0; t < 8; t++) {                 // B: 32 k x 64 n
            int v = tid + t * 256;
            int kl = v >> 6, n = v & 63;
            const float* src;
            if constexpr (MODE == MM_SIG)       src = &W[(size_t)(kt + kl) * 64 + n];
            else if constexpr (MODE == MM_GATE) src = &W[(size_t)(kt + kl) * 4096 + n0 + n];
            else                                src = &W[(size_t)(kt + kl) * 128 + n0 + n];
            cp4(bb + ((kl >> 2) * NB + n) * 16 + (kl & 3) * 4, src);
        }
    };

    // fragment offsets (validated layout from round-4 kernel)
    uint32_t aoff[4];
#pragma unroll
    for (int mt = 0; mt < 4; mt++)
        aoff[mt] = (uint32_t)((((lane >> 4) * 128) + wm * 64 + mt * 16 + (lane & 15)) * 16);
    uint32_t boff = (uint32_t)(((((lane >> 3) & 1) * NB) + wn * 16 +
                                (lane & 7) + ((lane >> 4) << 3)) * 16);

    float acc[4][2][4];
#pragma unroll
    for (int mt = 0; mt < 4; mt++)
#pragma unroll
        for (int nt = 0; nt < 2; nt++)
#pragma unroll
            for (int j = 0; j < 4; j++) acc[mt][nt][j] = 0.f;

    auto compute = [&](int st) {
        const uint32_t bufA = sbase + st * STG;
        const uint32_t bufB = bufA + ABUF;
#pragma unroll
        for (int s = 0; s < 4; s++) {                 // 4 k8-steps per chunk
            uint32_t a[4][4], b[4];
#pragma unroll
            for (int mt = 0; mt < 4; mt++)
                ldsm4(a[mt], bufA + aoff[mt] + s * (2 * 128 * 16));
            ldsm4(b, bufB + boff + s * (2 * NB * 16));
#pragma unroll
            for (int mt = 0; mt < 4; mt++) {
                mma8(acc[mt][0], a[mt], b[0], b[1]);
                mma8(acc[mt][1], a[mt], b[2], b[3]);
            }
        }
    };

    // ---- pipelined mainloop ----
#pragma unroll
    for (int s = 0; s < STAGES - 1; s++) { issue(s); cp_commit(); }
#pragma unroll 1
    for (int c = 0; c < NCH; c++) {
        cp_wait<STAGES - 2>();
        __syncthreads();
        if (c + STAGES - 1 < NCH) issue(c + STAGES - 1);
        cp_commit();
        compute(c & (STAGES - 1));
    }

    // ---- epilogue: fragments -> full-tile smem stage -> coalesced global ----
    __syncthreads();
    float* stage = (float*)smem;
#pragma unroll
    for (int mt = 0; mt < 4; mt++)
#pragma unroll
        for (int nt = 0; nt < 2; nt++) {
            int row = wm * 64 + mt * 16 + (lane >> 2);
            int col = wn * 16 + nt * 8 + 2 * (lane & 3);
            *(float2*)&stage[row * WNP + col]       = make_float2(acc[mt][nt][0], acc[mt][nt][1]);
            *(float2*)&stage[(row + 8) * WNP + col] = make_float2(acc[mt][nt][2], acc[mt][nt][3]);
        }
    __syncthreads();
#pragma unroll
    for (int t = 0; t < 8; t++) {
        int v = tid + t * 256;
        int row = v >> 4;
        int c4  = (v & 15) << 2;
        size_t rg = (size_t)(m0 + row);
        float4 d = *(float4*)&stage[row * WNP + c4];
        float dv[4] = {d.x, d.y, d.z, d.w};
        float o[4];
#pragma unroll
        for (int j = 0; j < 4; j++) {
            int n = c4 + j;
            if constexpr (MODE == MM_C0) {
                int ng = n0 + n;
                o[j] = X[rg * 128 + ng] * sigmoidf_(dv[j] + bias[ng]);
            } else if constexpr (MODE == MM_GATE) {
                int ng = n0 + n;
                o[j] = X[rg * 4096 + ng] * sigmoidf_(dv[j] + bias[ng]);
            } else {
                o[j] = dv[j] + bias[n];
            }
        }
        float4 ov = make_float4(o[0], o[1], o[2], o[3]);
        if constexpr (MODE == MM_C0)
            *(float4*)&g_content0[rg * 128 + n0 + c4] = ov;
        else if constexpr (MODE == MM_GATE)
            *(float4*)&g_mempre[rg * 4096 + n0 + c4] = ov;
        else
            *(float4*)&g_sig[rg * 192 + n0 + c4] = ov;
    }
}

// ====================== small SIMT GEMM (EZ / ZA) ======================
enum { M_EZ = 1, M_ZA = 4 };

template <int MODE, int BN, int TN, int KC, int LDA>
__global__ void __launch_bounds__(256) gemm_k(
    const float* __restrict__ W0, const float* __restrict__ W1,
    const float* __restrict__ b0, const float* __restrict__ b1)
{
    constexpr int BM = 128, BK = 16, TM = 8;
    __shared__ float As[BK][BM];
    __shared__ float Bs[BK][BN];

    const float* A = (MODE == M_EZ) ? g_content0 : g_zt;

    const int tid  = threadIdx.x;
    const int trow = tid >> 4;
    const int tcol = tid & 15;
    const int m0 = blockIdx.x * BM;

    float acc[TM][TN];
#pragma unroll
    for (int i = 0; i < TM; i++)
#pragma unroll
        for (int j = 0; j < TN; j++) acc[i][j] = 0.f;

    for (int kt = 0; kt < KC; kt += BK) {
#pragma unroll
        for (int v0 = 0; v0 < 2; v0++) {
            int v  = tid + v0 * 256;
            int r  = v >> 2;
            int c4 = (v & 3) * 4;
            float4 t = *(const float4*)&A[(size_t)(m0 + r) * LDA + kt + c4];
            As[c4 + 0][r] = t.x; As[c4 + 1][r] = t.y;
            As[c4 + 2][r] = t.z; As[c4 + 3][r] = t.w;
        }
        constexpr int BV = (BK * BN) / (4 * 256);
#pragma unroll
        for (int v0 = 0; v0 < BV; v0++) {
            int v  = tid + v0 * 256;
            int r  = v / (BN / 4);
            int c4 = (v % (BN / 4)) * 4;
            int kg = kt + r;
            float4 t;
            if constexpr (MODE == M_EZ) {
                int w = c4 >> 6, nc = c4 & 63;
                const float* W = (w == 0) ? W0 : W1;
                t = *(const float4*)&W[(size_t)kg * 64 + nc];
            } else {
                t = *(const float4*)&W0[(size_t)kg * 64 + c4];
            }
            *(float4*)&Bs[r][c4] = t;
        }
        __syncthreads();

#pragma unroll
        for (int kk = 0; kk < BK; kk++) {
            float a[TM], bv[TN];
#pragma unroll
            for (int i = 0; i < TM; i += 4) {
                float4 t = *(const float4*)&As[kk][trow * TM + i];
                a[i] = t.x; a[i + 1] = t.y; a[i + 2] = t.z; a[i + 3] = t.w;
            }
#pragma unroll
            for (int j = 0; j < TN; j += 4) {
                float4 t = *(const float4*)&Bs[kk][tcol * TN + j];
                bv[j] = t.x; bv[j + 1] = t.y; bv[j + 2] = t.z; bv[j + 3] = t.w;
            }
#pragma unroll
            for (int i = 0; i < TM; i++)
#pragma unroll
                for (int j = 0; j < TN; j++)
                    acc[i][j] = fmaf(a[i], bv[j], acc[i][j]);
        }
        __syncthreads();
    }

#pragma unroll
    for (int i = 0; i < TM; i++) {
        int rg = m0 + trow * TM + i;
#pragma unroll
        for (int j = 0; j < TN; j += 4) {
            int ng = tcol * TN + j;
            float4 o;
            if constexpr (MODE == M_EZ) {
                const float* bp = (ng < 64) ? (b0 + ng) : (b1 + (ng - 64));
                float4 bq = *(const float4*)bp;
                o.x = acc[i][j + 0] + bq.x; o.y = acc[i][j + 1] + bq.y;
                o.z = acc[i][j + 2] + bq.z; o.w = acc[i][j + 3] + bq.w;
                *(float4*)&g_c0ez[(size_t)rg * 128 + ng] = o;
            } else {
                float4 bq = *(const float4*)&b0[ng];
                o.x = acc[i][j + 0] + bq.x; o.y = acc[i][j + 1] + bq.y;
                o.z = acc[i][j + 2] + bq.z; o.w = acc[i][j + 3] + bq.w;
                *(float4*)&g_ztwza[(size_t)rg * 64 + ng] = o;
            }
        }
    }
}

// ---------------- write_weight: softmax(control_key @ memory_key^T) ----------------
__global__ void __launch_bounds__(256) ww_k(const float* __restrict__ ck,
                                            const float* __restrict__ mk)
{
    int g = threadIdx.x >> 6;
    int t = threadIdx.x & 63;
    int b = blockIdx.x * 4 + g;
    __shared__ float sck[4][64];
    __shared__ float pmax[4][2];
    __shared__ float psum[4][2];

    sck[g][t] = ck[b * 64 + t];
    __syncthreads();
    float dot = 0.f;
#pragma unroll 8
    for (int k = 0; k < 64; k++) dot = fmaf(sck[g][k], mk[t * 64 + k], dot);

    float mx = dot;
#pragma unroll
    for (int o = 16; o > 0; o >>= 1) mx = fmaxf(mx, __shfl_xor_sync(0xffffffffu, mx, o));
    int wl = t >> 5;
    if ((t & 31) == 0) pmax[g][wl] = mx;
    __syncthreads();
    mx = fmaxf(pmax[g][0], pmax[g][1]);

    float e = __expf(dot - mx);
    float s = e;
#pragma unroll
    for (int o = 16; o > 0; o >>= 1) s += __shfl_xor_sync(0xffffffffu, s, o);
    if ((t & 31) == 0) psum[g][wl] = s;
    __syncthreads();
    s = psum[g][0] + psum[g][1];

    g_ww[b * 64 + t] = e / s;
}

// ---------------- zt + erase ----------------
__global__ void __launch_bounds__(256) zt_erase_k()
{
    int i = blockIdx.x * 256 + threadIdx.x;
    int b = i >> 6, j = i & 63;
    float cwe  = g_c0ez[b * 128 + j];
    float cwz  = g_c0ez[b * 128 + 64 + j];
    float semv = g_sig[b * 192 + j];
    float szmv = g_sig[b * 192 + 64 + j];
    g_zt[i]    = sigmoidf_(cwz + szmv);
    g_erase[i] = sigmoidf_(sigmoidf_(cwe) + sigmoidf_(semv));
}

// ---------------- final: out = mempre*(1 - w*erase) + w*add ----------------
__global__ void __launch_bounds__(256) final_k(float* __restrict__ out)
{
    int b = blockIdx.x;
    int t = threadIdx.x;
    __shared__ float sww[64], ser[64], sadd[64];
    if (t < 64) {
        sww[t] = g_ww[b * 64 + t];
        ser[t] = g_erase[b * 64 + t];
        sadd[t] = tanhf(tanhf(g_ztwza[b * 64 + t]) + tanhf(g_sig[b * 192 + 128 + t]));
    }
    __syncthreads();
    const float4* mp = (const float4*)&g_mempre[(size_t)b * 4096];
    float4* op = (float4*)(out + (size_t)b * 4096);
#pragma unroll
    for (int it = 0; it < 4; it++) {
        int v  = t + it * 256;
        int m  = v >> 4;
        int dv = (v & 15) << 2;
        float w = sww[m];
        float4 x = mp[v];
        float4 r;
        r.x = x.x * (1.f - w * ser[dv + 0]) + w * sadd[dv + 0];
        r.y = x.y * (1.f - w * ser[dv + 1]) + w * sadd[dv + 1];
        r.z = x.z * (1.f - w * ser[dv + 2]) + w * sadd[dv + 2];
        r.w = x.w * (1.f - w * ser[dv + 3]) + w * sadd[dv + 3];
        op[v] = r;
    }
}

// ====================== launch ======================
extern "C" void kernel_launch(void* const* d_in, const int* in_sizes, int n_in,
                              void* d_out, int out_size)
{
    const float* control_key  = (const float*)d_in[0];
    const float* control_qa   = (const float*)d_in[1];
    const float* memory_key   = (const float*)d_in[2];
    const float* memory_value = (const float*)d_in[3];
    const float* We   = (const float*)d_in[4];
    const float* be   = (const float*)d_in[5];
    const float* Wemv = (const float*)d_in[6];
    const float* bemv = (const float*)d_in[7];
    const float* Wza  = (const float*)d_in[8];
    const float* bza  = (const float*)d_in[9];
    const float* Wamv = (const float*)d_in[10];
    const float* bamv = (const float*)d_in[11];
    const float* Wc0  = (const float*)d_in[12];
    const float* bc0  = (const float*)d_in[13];
    const float* Wm1  = (const float*)d_in[14];
    const float* bm1  = (const float*)d_in[15];
    const float* Wz   = (const float*)d_in[16];
    const float* bz   = (const float*)d_in[17];
    const float* Wzmv = (const float*)d_in[18];
    const float* bzmv = (const float*)d_in[19];
    float* out = (float*)d_out;

    constexpr int SMEM = 4 * (128 * 32 * 4 + 64 * 32 * 4);  // 98304

    cudaFuncSetAttribute(mma_k<MM_C0, 4096, 4096>,
                         cudaFuncAttributeMaxDynamicSharedMemorySize, SMEM);
    cudaFuncSetAttribute(mma_k<MM_GATE, 128, 128>,
                         cudaFuncAttributeMaxDynamicSharedMemorySize, SMEM);
    cudaFuncSetAttribute(mma_k<MM_SIG, 4096, 4096>,
                         cudaFuncAttributeMaxDynamicSharedMemorySize, SMEM);

    // write weights (independent)
    ww_k<<<BB / 4, 256>>>(control_key, memory_key);

    // content0 = qa * sigmoid(memory_value @ Wc0 + bc0)   [B x 128]
    mma_k<MM_C0, 4096, 4096><<<dim3(2, 128), 256, SMEM>>>(
        memory_value, Wc0, nullptr, nullptr, bc0, nullptr, nullptr, control_qa);

    // c0ez = [c0@We + be | c0@Wz + bz]                    [B x 128]
    gemm_k<M_EZ, 128, 8, 128, 128><<<dim3(BB / 128, 1), 256>>>(We, Wz, be, bz);

    // mempre = memory_value * sigmoid(c0 @ Wm1 + bm1)     [B x 4096]
    mma_k<MM_GATE, 128, 128><<<dim3(64, 128), 256, SMEM>>>(
        nullptr, Wm1, nullptr, nullptr, bm1, nullptr, nullptr, memory_value);

    // sig = mempre @ [Wemv|Wzmv|Wamv] + biases            [B x 192]
    mma_k<MM_SIG, 4096, 4096><<<dim3(3, 128), 256, SMEM>>>(
        nullptr, Wemv, Wzmv, Wamv, bemv, bzmv, bamv, nullptr);

    // zt, erase
    zt_erase_k<<<BB * 64 / 256, 256>>>();

    // ztwza = zt @ Wza + bza                               [B x 64]
    gemm_k<M_ZA, 64, 4, 64, 64><<<dim3(BB / 128, 1), 256>>>(Wza, nullptr, bza, nullptr);

    // final elementwise
    final_k<<<BB, 256>>>(out);
}

// round 6
// speedup vs baseline: 1.0678x; 1.0678x over previous
#include <cuda_runtime.h>
#include <math.h>
#include <stdint.h>

#define BB 16384

// ---------------- scratch (device globals; no allocs allowed) ----------------
__device__ float g_mempre[(size_t)BB * 4096];   // 256 MB
__device__ float g_ww[BB * 64];                 //   4 MB

__device__ __forceinline__ float sigmoidf_(float x) { return 1.0f / (1.0f + __expf(-x)); }

__device__ __forceinline__ uint32_t smem_u32(const void* p) {
    uint32_t a;
    asm("{ .reg .u64 t; cvta.to.shared.u64 t, %1; cvt.u32.u64 %0, t; }" : "=r"(a) : "l"(p));
    return a;
}
__device__ __forceinline__ void ldsm4(uint32_t* d, uint32_t addr) {
    asm volatile("ldmatrix.sync.aligned.m8n8.x4.shared.b16 {%0,%1,%2,%3}, [%4];"
        : "=r"(d[0]), "=r"(d[1]), "=r"(d[2]), "=r"(d[3]) : "r"(addr));
}
__device__ __forceinline__ void ldsm2(uint32_t* d, uint32_t addr) {
    asm volatile("ldmatrix.sync.aligned.m8n8.x2.shared.b16 {%0,%1}, [%2];"
        : "=r"(d[0]), "=r"(d[1]) : "r"(addr));
}
__device__ __forceinline__ void mma8(float* c, const uint32_t* a, uint32_t b0, uint32_t b1) {
    asm volatile("mma.sync.aligned.m16n8k8.row.col.f32.tf32.tf32.f32 "
        "{%0,%1,%2,%3}, {%4,%5,%6,%7}, {%8,%9}, {%0,%1,%2,%3};"
        : "+f"(c[0]), "+f"(c[1]), "+f"(c[2]), "+f"(c[3])
        : "r"(a[0]), "r"(a[1]), "r"(a[2]), "r"(a[3]), "r"(b0), "r"(b1));
}
__device__ __forceinline__ void cp16(uint32_t dst, const void* src) {
    asm volatile("cp.async.cg.shared.global [%0], [%1], 16;" :: "r"(dst), "l"(src));
}
__device__ __forceinline__ void cp4(uint32_t dst, const void* src) {
    asm volatile("cp.async.ca.shared.global [%0], [%1], 4;" :: "r"(dst), "l"(src));
}
__device__ __forceinline__ void cp_commit() {
    asm volatile("cp.async.commit_group;" ::: "memory");
}
__device__ __forceinline__ void cp_wait_all() {
    asm volatile("cp.async.wait_group 0;" ::: "memory");
}
// B-operand ldmatrix.x4 offset: covers 2 n8-tiles (pair p) x 2 k-blocks
__device__ __forceinline__ uint32_t boff4(int NB, int wn, int NW, int p, int lane) {
    return (uint32_t)(((((lane >> 3) & 1) * NB) + wn * NW + p * 16 +
                      (lane & 7) + ((lane >> 4) << 3)) * 16);
}

// ---------------- SMEM layout (dynamic, bytes) ----------------
// [0,      65536)  c0 chunks (K=128 tf32 A-operand); later: erase[128*64] @0, z1/add[128*64] @32768
// [65536,  81920)  32-k A-operand chunk buffer (mempre chunk / zt half-chunk / Wza B)
// [81920, 196608)  stage region (pipeline buffers / dumps)
#define C0_OFF 0
#define MP_OFF 65536
#define ST_OFF 81920
#define SMEM_TOTAL 196608

// ====================== the fused row-block kernel ======================
// 128 CTAs x 512 threads; CTA owns rows [m0, m0+128). Warps: 4M x 4N.
__global__ void __launch_bounds__(512, 1) fused_k(
    const float* __restrict__ qa,  const float* __restrict__ mv,
    const float* __restrict__ We,  const float* __restrict__ be,
    const float* __restrict__ Wemv, const float* __restrict__ bemv,
    const float* __restrict__ Wza, const float* __restrict__ bza,
    const float* __restrict__ Wamv, const float* __restrict__ bamv,
    const float* __restrict__ Wc0, const float* __restrict__ bc0,
    const float* __restrict__ Wm1, const float* __restrict__ bm1,
    const float* __restrict__ Wz,  const float* __restrict__ bz,
    const float* __restrict__ Wzmv, const float* __restrict__ bzmv,
    float* __restrict__ outp)
{
    extern __shared__ char smem[];
    const int tid  = threadIdx.x;
    const int lane = tid & 31;
    const int wid  = tid >> 5;
    const int wm   = wid & 3;     // 4 M-groups of 32 rows
    const int wn   = wid >> 2;    // 4 N-groups
    const int m0   = blockIdx.x * 128;

    uint32_t sb  = smem_u32(smem);
    uint32_t c0b = sb + C0_OFF;
    uint32_t mpb = sb + MP_OFF;
    uint32_t stb = sb + ST_OFF;

    // A-fragment ldmatrix offsets (all A operands: 128 rows, chunk (kb*128+row)*16)
    const uint32_t aoff0 = (uint32_t)((((lane >> 4) * 128) + wm * 32 + (lane & 15)) * 16);
    const uint32_t aoff1 = aoff0 + 256;   // mt=1: +16 rows

    const int frow0 = wm * 32 + (lane >> 2);   // fragment base row (mt adds 16, half adds 8)
    const int fc2   = 2 * (lane & 3);          // fragment base col within n8 tile

    // ============ P1: c0 = qa * sigmoid(mv @ Wc0 + bc0) ============
    {
        float cacc[2][4][4];
#pragma unroll
        for (int mt = 0; mt < 2; mt++)
#pragma unroll
            for (int nt = 0; nt < 4; nt++)
#pragma unroll
                for (int j = 0; j < 4; j++) cacc[mt][nt][j] = 0.f;

        auto issue = [&](int c) {
            uint32_t ab = stb + (c & 1) * 32768, bb = ab + 16384;
            int kt = c * 32;
#pragma unroll
            for (int i = 0; i < 2; i++) {              // A: mv 128x32
                int v = tid + i * 512;
                int kq = v & 7, r = v >> 3;
                cp16(ab + (kq * 128 + r) * 16, &mv[(size_t)(m0 + r) * 4096 + kt + kq * 4]);
            }
#pragma unroll
            for (int i = 0; i < 8; i++) {              // B: Wc0 32x128
                int v = tid + i * 512;
                int kl = v >> 7, n = v & 127;
                cp4(bb + ((kl >> 2) * 128 + n) * 16 + (kl & 3) * 4,
                    &Wc0[(size_t)(kt + kl) * 128 + n]);
            }
            cp_commit();
        };

        issue(0);
#pragma unroll 1
        for (int c = 0; c < 128; c++) {
            cp_wait_all();
            __syncthreads();
            if (c < 127) issue(c + 1);
            uint32_t ab = stb + (c & 1) * 32768, bb = ab + 16384;
#pragma unroll
            for (int s = 0; s < 4; s++) {
                uint32_t a0[4], a1[4];
                ldsm4(a0, ab + aoff0 + s * 4096);
                ldsm4(a1, ab + aoff1 + s * 4096);
#pragma unroll
                for (int p = 0; p < 2; p++) {
                    uint32_t b[4];
                    ldsm4(b, bb + boff4(128, wn, 32, p, lane) + s * 4096);
                    mma8(cacc[0][2 * p],     a0, b[0], b[1]);
                    mma8(cacc[0][2 * p + 1], a0, b[2], b[3]);
                    mma8(cacc[1][2 * p],     a1, b[0], b[1]);
                    mma8(cacc[1][2 * p + 1], a1, b[2], b[3]);
                }
            }
        }
        // epilogue: fragments -> stage[128][132] -> c0 chunks (with qa * sigmoid(+bc0))
        __syncthreads();
        float* stg = (float*)(smem + ST_OFF);
#pragma unroll
        for (int mt = 0; mt < 2; mt++)
#pragma unroll
            for (int nt = 0; nt < 4; nt++) {
                int row = frow0 + mt * 16;
                int col = wn * 32 + nt * 8 + fc2;
                *(float2*)&stg[row * 132 + col]       = make_float2(cacc[mt][nt][0], cacc[mt][nt][1]);
                *(float2*)&stg[(row + 8) * 132 + col] = make_float2(cacc[mt][nt][2], cacc[mt][nt][3]);
            }
        __syncthreads();
#pragma unroll
        for (int i = 0; i < 32; i++) {
            int v = tid + i * 512;
            int row = v >> 7, k = v & 127;
            float c0v = __ldg(&qa[(size_t)(m0 + row) * 128 + k]) *
                        sigmoidf_(stg[row * 132 + k] + __ldg(&bc0[k]));
            *(float*)(smem + C0_OFF + ((k >> 2) * 128 + row) * 16 + (k & 3) * 4) = c0v;
        }
        __syncthreads();
    }

    // ============ P3: gate/mempre + SIG accumulation (K-loop over 4096) ============
    float sacc[2][6][4];
#pragma unroll
    for (int mt = 0; mt < 2; mt++)
#pragma unroll
        for (int nt = 0; nt < 6; nt++)
#pragma unroll
            for (int j = 0; j < 4; j++) sacc[mt][nt][j] = 0.f;
    {
        auto issue = [&](int c) {
            uint32_t base = stb + (c & 1) * 57344;
            int kt = c * 32;
#pragma unroll
            for (int i = 0; i < 2; i++) {              // mv chunk 128x32 (A-chunk layout)
                int v = tid + i * 512;
                int kq = v & 7, r = v >> 3;
                cp16(base + (kq * 128 + r) * 16, &mv[(size_t)(m0 + r) * 4096 + kt + kq * 4]);
            }
#pragma unroll
            for (int i = 0; i < 8; i++) {              // Wm1[:,kt:kt+32]: 128k x 32n
                int v = tid + i * 512;
                int kl = v >> 5, n = v & 31;
                cp4(base + 16384 + ((kl >> 2) * 32 + n) * 16 + (kl & 3) * 4,
                    &Wm1[(size_t)kl * 4096 + kt + n]);
            }
#pragma unroll
            for (int i = 0; i < 12; i++) {             // [Wemv|Wzmv|Wamv] chunk: 32k x 192n
                int v = tid + i * 512;
                int kl = v / 192, n = v - kl * 192;
                const float* W = (n < 64) ? Wemv : (n < 128) ? Wzmv : Wamv;
                cp4(base + 32768 + ((kl >> 2) * 192 + n) * 16 + (kl & 3) * 4,
                    &W[(size_t)(kt + kl) * 64 + (n & 63)]);
            }
            cp_commit();
        };
        const uint32_t gboff = (uint32_t)(((((lane >> 3) & 1) * 32) + wn * 8 + (lane & 7)) * 16);

        issue(0);
#pragma unroll 1
        for (int c = 0; c < 128; c++) {
            cp_wait_all();
            __syncthreads();
            if (c < 127) issue(c + 1);
            uint32_t base = stb + (c & 1) * 57344;
            int kt = c * 32;

            // gate mma: A = c0 (K=128), B = Wm1 chunk (NB=32)
            float gacc[2][4];
#pragma unroll
            for (int mt = 0; mt < 2; mt++)
#pragma unroll
                for (int j = 0; j < 4; j++) gacc[mt][j] = 0.f;
#pragma unroll
            for (int s = 0; s < 16; s++) {
                uint32_t a0[4], a1[4], b[2];
                ldsm4(a0, c0b + aoff0 + s * 4096);
                ldsm4(a1, c0b + aoff1 + s * 4096);
                ldsm2(b, base + 16384 + gboff + s * 1024);
                mma8(gacc[0], a0, b[0], b[1]);
                mma8(gacc[1], a1, b[0], b[1]);
            }
            // mempre chunk = mv * sigmoid(gate + bm1) -> SMEM A-chunk
#pragma unroll
            for (int mt = 0; mt < 2; mt++)
#pragma unroll
                for (int idx = 0; idx < 4; idx++) {
                    int row = frow0 + mt * 16 + (idx >> 1) * 8;
                    int col = wn * 8 + fc2 + (idx & 1);
                    float gv = sigmoidf_(gacc[mt][idx] + __ldg(&bm1[kt + col]));
                    uint32_t off = ((col >> 2) * 128 + row) * 16 + (col & 3) * 4;
                    float mvv = *(float*)(smem + ST_OFF + (c & 1) * 57344 + off);
                    *(float*)(smem + MP_OFF + off) = mvv * gv;
                }
            __syncthreads();
            // write mempre chunk to gmem (coalesced float4)
#pragma unroll
            for (int i = 0; i < 2; i++) {
                int v = tid + i * 512;
                int row = v >> 3, kb = v & 7;
                float4 t = *(float4*)(smem + MP_OFF + (kb * 128 + row) * 16);
                *(float4*)&g_mempre[(size_t)(m0 + row) * 4096 + kt + kb * 4] = t;
            }
            // SIG mma: A = mempre chunk (K=32), B = Wsig chunk (NB=192)
#pragma unroll
            for (int s = 0; s < 4; s++) {
                uint32_t a0[4], a1[4];
                ldsm4(a0, mpb + aoff0 + s * 4096);
                ldsm4(a1, mpb + aoff1 + s * 4096);
#pragma unroll
                for (int p = 0; p < 3; p++) {
                    uint32_t b[4];
                    ldsm4(b, base + 32768 + boff4(192, wn, 48, p, lane) + s * 6144);
                    mma8(sacc[0][2 * p],     a0, b[0], b[1]);
                    mma8(sacc[0][2 * p + 1], a0, b[2], b[3]);
                    mma8(sacc[1][2 * p],     a1, b[0], b[1]);
                    mma8(sacc[1][2 * p + 1], a1, b[2], b[3]);
                }
            }
        }
    }

    // ============ P4a: EZ = c0 @ [We|Wz] (c0 still resident) ============
    __syncthreads();
    {
#pragma unroll
        for (int i = 0; i < 32; i++) {                 // B-chunk: 128k x 128n at stage
            int v = tid + i * 512;
            int kl = v >> 7, n = v & 127;
            const float* W = (n < 64) ? We : Wz;
            cp4(stb + ((kl >> 2) * 128 + n) * 16 + (kl & 3) * 4,
                &W[(size_t)kl * 64 + (n & 63)]);
        }
        cp_commit();
        cp_wait_all();
        __syncthreads();

        float ezacc[2][4][4];
#pragma unroll
        for (int mt = 0; mt < 2; mt++)
#pragma unroll
            for (int nt = 0; nt < 4; nt++)
#pragma unroll
                for (int j = 0; j < 4; j++) ezacc[mt][nt][j] = 0.f;
#pragma unroll
        for (int s = 0; s < 16; s++) {
            uint32_t a0[4], a1[4];
            ldsm4(a0, c0b + aoff0 + s * 4096);
            ldsm4(a1, c0b + aoff1 + s * 4096);
#pragma unroll
            for (int p = 0; p < 2; p++) {
                uint32_t b[4];
                ldsm4(b, stb + boff4(128, wn, 32, p, lane) + s * 4096);
                mma8(ezacc[0][2 * p],     a0, b[0], b[1]);
                mma8(ezacc[0][2 * p + 1], a0, b[2], b[3]);
                mma8(ezacc[1][2 * p],     a1, b[0], b[1]);
                mma8(ezacc[1][2 * p + 1], a1, b[2], b[3]);
            }
        }
        __syncthreads();   // c0 dead; stage B dead

        // dump: e1=sigmoid(c0@We+be) at c0 area[0..32K), z1=c0@Wz+bz at [32K..64K)
        float* e1a = (float*)(smem + C0_OFF);
        float* z1a = (float*)(smem + C0_OFF + 32768);
#pragma unroll
        for (int mt = 0; mt < 2; mt++)
#pragma unroll
            for (int nt = 0; nt < 4; nt++)
#pragma unroll
                for (int idx = 0; idx < 4; idx++) {
                    int row = frow0 + mt * 16 + (idx >> 1) * 8;
                    int col = wn * 32 + nt * 8 + fc2 + (idx & 1);
                    float v = ezacc[mt][nt][idx];
                    if (col < 64) e1a[row * 64 + col] = sigmoidf_(v + __ldg(&be[col]));
                    else          z1a[row * 64 + (col - 64)] = v + __ldg(&bz[col - 64]);
                }
        // dump SIG accs (+bias) -> sig stage [128][192]
        float* siga = (float*)(smem + ST_OFF);
#pragma unroll
        for (int mt = 0; mt < 2; mt++)
#pragma unroll
            for (int nt = 0; nt < 6; nt++)
#pragma unroll
                for (int idx = 0; idx < 4; idx++) {
                    int row = frow0 + mt * 16 + (idx >> 1) * 8;
                    int col = wn * 48 + nt * 8 + fc2 + (idx & 1);
                    float bv = (col < 64) ? __ldg(&bemv[col])
                             : (col < 128) ? __ldg(&bzmv[col - 64])
                                           : __ldg(&bamv[col - 128]);
                    siga[row * 192 + col] = sacc[mt][nt][idx] + bv;
                }
        __syncthreads();
    }

    // ============ P4b: zt, erase; add = tanh(tanh(zt@Wza+bza)+tanh(samv)) ============
    {
        float* e1a  = (float*)(smem + C0_OFF);            // becomes erase in place
        float* z1a  = (float*)(smem + C0_OFF + 32768);    // becomes add later
        float* siga = (float*)(smem + ST_OFF);

        float zaacc[2][2][4];
#pragma unroll
        for (int mt = 0; mt < 2; mt++)
#pragma unroll
            for (int nt = 0; nt < 2; nt++)
#pragma unroll
                for (int j = 0; j < 4; j++) zaacc[mt][nt][j] = 0.f;

#pragma unroll 1
        for (int h = 0; h < 2; h++) {
            // Wza half B-chunk: 32k x 64n at stage+98304 (8KB)
#pragma unroll
            for (int i = 0; i < 4; i++) {
                int v = tid + i * 512;
                int kl = v >> 6, n = v & 63;
                cp4(stb + 98304 + ((kl >> 2) * 64 + n) * 16 + (kl & 3) * 4,
                    &Wza[(size_t)(h * 32 + kl) * 64 + n]);
            }
            cp_commit();
            // element pass: zt half -> MP chunk; erase half in place (h covers cols)
#pragma unroll
            for (int i = 0; i < 8; i++) {
                int v = tid + i * 512;
                int row = v >> 5, jl = v & 31;
                int j = h * 32 + jl;
                float ztv = sigmoidf_(z1a[row * 64 + j] + siga[row * 192 + 64 + j]);
                *(float*)(smem + MP_OFF + ((jl >> 2) * 128 + row) * 16 + (jl & 3) * 4) = ztv;
                float erv = sigmoidf_(e1a[row * 64 + j] + sigmoidf_(siga[row * 192 + j]));
                e1a[row * 64 + j] = erv;
            }
            cp_wait_all();
            __syncthreads();
            // ZA mma accumulate: A = zt half chunk (K=32), B NB=64
#pragma unroll
            for (int s = 0; s < 4; s++) {
                uint32_t a0[4], a1[4], b[4];
                ldsm4(a0, mpb + aoff0 + s * 4096);
                ldsm4(a1, mpb + aoff1 + s * 4096);
                ldsm4(b, stb + 98304 + boff4(64, wn, 16, 0, lane) + s * 2048);
                mma8(zaacc[0][0], a0, b[0], b[1]);
                mma8(zaacc[0][1], a0, b[2], b[3]);
                mma8(zaacc[1][0], a1, b[0], b[1]);
                mma8(zaacc[1][1], a1, b[2], b[3]);
            }
            __syncthreads();
        }
        // ZA epilogue: add -> z1 area
#pragma unroll
        for (int mt = 0; mt < 2; mt++)
#pragma unroll
            for (int nt = 0; nt < 2; nt++)
#pragma unroll
                for (int idx = 0; idx < 4; idx++) {
                    int row = frow0 + mt * 16 + (idx >> 1) * 8;
                    int col = wn * 16 + nt * 8 + fc2 + (idx & 1);
                    float samv = siga[row * 192 + 128 + col];
                    float addv = tanhf(tanhf(zaacc[mt][nt][idx] + __ldg(&bza[col])) + tanhf(samv));
                    z1a[row * 64 + col] = addv;
                }
        __syncthreads();
        // load write-weights -> stage (sig dead)
#pragma unroll
        for (int i = 0; i < 4; i++) {
            int v = tid + i * 512;     // 2048 float4 tasks = 128x64 floats
            *(float4*)(smem + ST_OFF + v * 16) = *(const float4*)&g_ww[(size_t)m0 * 64 + v * 4];
        }
        __syncthreads();
    }

    // ============ P5: out = mempre*(1 - w*erase) + w*add ============
    {
        const float* er = (const float*)(smem + C0_OFF);
        const float* ad = (const float*)(smem + C0_OFF + 32768);
        const float* sw = (const float*)(smem + ST_OFF);
#pragma unroll 4
        for (int it = 0; it < 256; it++) {
            int v = tid + it * 512;
            int row = v >> 10, q = v & 1023;
            float4 mp = *(const float4*)&g_mempre[(size_t)(m0 + row) * 4096 + q * 4];
            float w = sw[row * 64 + (q >> 4)];
            float4 e4 = *(const float4*)&er[row * 64 + (q & 15) * 4];
            float4 a4 = *(const float4*)&ad[row * 64 + (q & 15) * 4];
            float4 r;
            r.x = mp.x * (1.f - w * e4.x) + w * a4.x;
            r.y = mp.y * (1.f - w * e4.y) + w * a4.y;
            r.z = mp.z * (1.f - w * e4.z) + w * a4.z;
            r.w = mp.w * (1.f - w * e4.w) + w * a4.w;
            *(float4*)&outp[(size_t)(m0 + row) * 4096 + q * 4] = r;
        }
    }
}

// ---------------- write_weight: softmax(control_key @ memory_key^T) ----------------
__global__ void __launch_bounds__(256) ww_k(const float* __restrict__ ck,
                                            const float* __restrict__ mk)
{
    int g = threadIdx.x >> 6;
    int t = threadIdx.x & 63;
    int b = blockIdx.x * 4 + g;
    __shared__ float sck[4][64];
    __shared__ float pmax[4][2];
    __shared__ float psum[4][2];

    sck[g][t] = ck[b * 64 + t];
    __syncthreads();
    float dot = 0.f;
#pragma unroll 8
    for (int k = 0; k < 64; k++) dot = fmaf(sck[g][k], mk[t * 64 + k], dot);

    float mx = dot;
#pragma unroll
    for (int o = 16; o > 0; o >>= 1) mx = fmaxf(mx, __shfl_xor_sync(0xffffffffu, mx, o));
    int wl = t >> 5;
    if ((t & 31) == 0) pmax[g][wl] = mx;
    __syncthreads();
    mx = fmaxf(pmax[g][0], pmax[g][1]);

    float e = __expf(dot - mx);
    float s = e;
#pragma unroll
    for (int o = 16; o > 0; o >>= 1) s += __shfl_xor_sync(0xffffffffu, s, o);
    if ((t & 31) == 0) psum[g][wl] = s;
    __syncthreads();
    s = psum[g][0] + psum[g][1];

    g_ww[b * 64 + t] = e / s;
}

// ====================== launch ======================
extern "C" void kernel_launch(void* const* d_in, const int* in_sizes, int n_in,
                              void* d_out, int out_size)
{
    const float* control_key  = (const float*)d_in[0];
    const float* control_qa   = (const float*)d_in[1];
    const float* memory_key   = (const float*)d_in[2];
    const float* memory_value = (const float*)d_in[3];
    const float* We   = (const float*)d_in[4];
    const float* be   = (const float*)d_in[5];
    const float* Wemv = (const float*)d_in[6];
    const float* bemv = (const float*)d_in[7];
    const float* Wza  = (const float*)d_in[8];
    const float* bza  = (const float*)d_in[9];
    const float* Wamv = (const float*)d_in[10];
    const float* bamv = (const float*)d_in[11];
    const float* Wc0  = (const float*)d_in[12];
    const float* bc0  = (const float*)d_in[13];
    const float* Wm1  = (const float*)d_in[14];
    const float* bm1  = (const float*)d_in[15];
    const float* Wz   = (const float*)d_in[16];
    const float* bz   = (const float*)d_in[17];
    const float* Wzmv = (const float*)d_in[18];
    const float* bzmv = (const float*)d_in[19];
    float* out = (float*)d_out;

    cudaFuncSetAttribute(fused_k, cudaFuncAttributeMaxDynamicSharedMemorySize, SMEM_TOTAL);

    // write weights (independent, consumed by fused_k P5)
    ww_k<<<BB / 4, 256>>>(control_key, memory_key);

    // everything else, fused per 128-row block
    fused_k<<<BB / 128, 512, SMEM_TOTAL>>>(
        control_qa, memory_value,
        We, be, Wemv, bemv, Wza, bza, Wamv, bamv,
        Wc0, bc0, Wm1, bm1, Wz, bz, Wzmv, bzmv,
        out);
}

// round 7
// speedup vs baseline: 1.1755x; 1.1009x over previous
#include <cuda_runtime.h>
#include <math.h>
#include <stdint.h>

#define BB 16384

__device__ float g_mempre[(size_t)BB * 4096];   // 256 MB
__device__ float g_ww[BB * 64];                 //   4 MB

__device__ __forceinline__ float sigmoidf_(float x) { return 1.0f / (1.0f + __expf(-x)); }

__device__ __forceinline__ uint32_t smem_u32(const void* p) {
    uint32_t a;
    asm("{ .reg .u64 t; cvta.to.shared.u64 t, %1; cvt.u32.u64 %0, t; }" : "=r"(a) : "l"(p));
    return a;
}
__device__ __forceinline__ void ldsm4(uint32_t* d, uint32_t addr) {
    asm volatile("ldmatrix.sync.aligned.m8n8.x4.shared.b16 {%0,%1,%2,%3}, [%4];"
        : "=r"(d[0]), "=r"(d[1]), "=r"(d[2]), "=r"(d[3]) : "r"(addr));
}
__device__ __forceinline__ void mma8(float* c, const uint32_t* a, uint32_t b0, uint32_t b1) {
    asm volatile("mma.sync.aligned.m16n8k8.row.col.f32.tf32.tf32.f32 "
        "{%0,%1,%2,%3}, {%4,%5,%6,%7}, {%8,%9}, {%0,%1,%2,%3};"
        : "+f"(c[0]), "+f"(c[1]), "+f"(c[2]), "+f"(c[3])
        : "r"(a[0]), "r"(a[1]), "r"(a[2]), "r"(a[3]), "r"(b0), "r"(b1));
}
__device__ __forceinline__ void cp16(uint32_t dst, const void* src) {
    asm volatile("cp.async.cg.shared.global [%0], [%1], 16;" :: "r"(dst), "l"(src));
}
__device__ __forceinline__ void cp4(uint32_t dst, const void* src) {
    asm volatile("cp.async.ca.shared.global [%0], [%1], 4;" :: "r"(dst), "l"(src));
}
__device__ __forceinline__ void cp_commit() {
    asm volatile("cp.async.commit_group;" ::: "memory");
}
template <int N>
__device__ __forceinline__ void cp_wait() {
    asm volatile("cp.async.wait_group %0;" :: "n"(N) : "memory");
}
__device__ __forceinline__ uint32_t boff4(int NB, int wn, int NW, int p, int lane) {
    return (uint32_t)(((((lane >> 3) & 1) * NB) + wn * NW + p * 16 +
                      (lane & 7) + ((lane >> 4) << 3)) * 16);
}
// swizzled R1 chunk address (banks spread for kb-strided access; row-dependent
// banks for ldsm unchanged since (row+16)^m == (row^m)+16 for m<8)
__device__ __forceinline__ uint32_t r1a(int kb, int row) {
    return (uint32_t)((kb * 128 + (row ^ (kb & 7))) * 16);
}

// ---- SMEM map (bytes) ----
// [0,65536)        c0 chunks (plain A-chunk); later e1 @0 (32K), z1/add @32768
// [65536,131072)   R1: 2x32KB mv/mempre bufs (swizzled); later siga 96KB @65536
// [131072,163840)  R2: Wm1 64-col slice (B-chunk, NB=64)
// [163840,212992)  R3: 2x24KB Wsig sub bufs; later EZ B buf @163840 (32K),
//                      zt chunk @163840 (16K), Wza half @180224 (8K)
// [188416,221184)  ww buffer (P5)
// P1 uses [65536,163840) as 3x32KB pipeline buffers; stage @65536 for c0 epi.
#define SMEM_TOTAL 221184

__global__ void __launch_bounds__(512, 1) fused_k(
    const float* __restrict__ qa,  const float* __restrict__ mv,
    const float* __restrict__ We,  const float* __restrict__ be,
    const float* __restrict__ Wemv, const float* __restrict__ bemv,
    const float* __restrict__ Wza, const float* __restrict__ bza,
    const float* __restrict__ Wamv, const float* __restrict__ bamv,
    const float* __restrict__ Wc0, const float* __restrict__ bc0,
    const float* __restrict__ Wm1, const float* __restrict__ bm1,
    const float* __restrict__ Wz,  const float* __restrict__ bz,
    const float* __restrict__ Wzmv, const float* __restrict__ bzmv,
    float* __restrict__ outp)
{
    extern __shared__ char smem[];
    const int tid  = threadIdx.x;
    const int lane = tid & 31;
    const int wid  = tid >> 5;
    const int wm   = wid & 3;
    const int wn   = wid >> 2;
    const int m0   = blockIdx.x * 128;

    uint32_t sb  = smem_u32(smem);
    uint32_t c0b = sb;

    const uint32_t aoff0 = (uint32_t)((((lane >> 4) * 128) + wm * 32 + (lane & 15)) * 16);
    const uint32_t aoff1 = aoff0 + 256;
    const uint32_t gbo   = boff4(64, wn, 16, 0, lane);
    const int frow0 = wm * 32 + (lane >> 2);
    const int fc2   = 2 * (lane & 3);

    // ============ P1: c0 = qa * sigmoid(mv @ Wc0 + bc0), 3-stage pipeline ============
    {
        float cacc[2][4][4];
#pragma unroll
        for (int mt = 0; mt < 2; mt++)
#pragma unroll
            for (int nt = 0; nt < 4; nt++)
#pragma unroll
                for (int j = 0; j < 4; j++) cacc[mt][nt][j] = 0.f;

        auto issue1 = [&](int c) {
            uint32_t ab = sb + 65536 + (c % 3) * 32768, bb2 = ab + 16384;
            int kt = c * 32;
#pragma unroll
            for (int i = 0; i < 2; i++) {
                int v = tid + i * 512;
                int kq = v & 7, r = v >> 3;
                cp16(ab + (kq * 128 + r) * 16, &mv[(size_t)(m0 + r) * 4096 + kt + kq * 4]);
            }
#pragma unroll
            for (int i = 0; i < 8; i++) {
                int v = tid + i * 512;
                int kl = v >> 7, n = v & 127;
                cp4(bb2 + ((kl >> 2) * 128 + n) * 16 + (kl & 3) * 4,
                    &Wc0[(size_t)(kt + kl) * 128 + n]);
            }
            cp_commit();
        };
        issue1(0); issue1(1);
#pragma unroll 1
        for (int c = 0; c < 128; c++) {
            if (c == 127) cp_wait<0>(); else cp_wait<1>();
            __syncthreads();
            if (c + 2 < 128) issue1(c + 2);
            uint32_t ab = sb + 65536 + (c % 3) * 32768, bb2 = ab + 16384;
#pragma unroll
            for (int s = 0; s < 4; s++) {
                uint32_t a0[4], a1[4];
                ldsm4(a0, ab + aoff0 + s * 4096);
                ldsm4(a1, ab + aoff1 + s * 4096);
#pragma unroll
                for (int p = 0; p < 2; p++) {
                    uint32_t b[4];
                    ldsm4(b, bb2 + boff4(128, wn, 32, p, lane) + s * 4096);
                    mma8(cacc[0][2 * p],     a0, b[0], b[1]);
                    mma8(cacc[0][2 * p + 1], a0, b[2], b[3]);
                    mma8(cacc[1][2 * p],     a1, b[0], b[1]);
                    mma8(cacc[1][2 * p + 1], a1, b[2], b[3]);
                }
            }
        }
        __syncthreads();
        float* stg = (float*)(smem + 65536);
#pragma unroll
        for (int mt = 0; mt < 2; mt++)
#pragma unroll
            for (int nt = 0; nt < 4; nt++) {
                int row = frow0 + mt * 16;
                int col = wn * 32 + nt * 8 + fc2;
                *(float2*)&stg[row * 132 + col]       = make_float2(cacc[mt][nt][0], cacc[mt][nt][1]);
                *(float2*)&stg[(row + 8) * 132 + col] = make_float2(cacc[mt][nt][2], cacc[mt][nt][3]);
            }
        __syncthreads();
#pragma unroll
        for (int i = 0; i < 32; i++) {
            int v = tid + i * 512;
            int row = v >> 7, k = v & 127;
            float c0v = __ldg(&qa[(size_t)(m0 + row) * 128 + k]) *
                        sigmoidf_(stg[row * 132 + k] + __ldg(&bc0[k]));
            *(float*)(smem + ((k >> 2) * 128 + row) * 16 + (k & 3) * 4) = c0v;
        }
        __syncthreads();
    }

    // ============ P3: per 64-col block: gate -> mempre(inplace) -> SIG accumulate ============
    float sacc[2][6][4];
#pragma unroll
    for (int mt = 0; mt < 2; mt++)
#pragma unroll
        for (int nt = 0; nt < 6; nt++)
#pragma unroll
            for (int j = 0; j < 4; j++) sacc[mt][nt][j] = 0.f;
    {
        auto issue_mw = [&](int o) {
            uint32_t r1b_ = sb + 65536 + (o & 1) * 32768;
            int kt = o * 64;
#pragma unroll
            for (int i = 0; i < 4; i++) {
                int v = tid + i * 512;
                int kb = v & 15, row = v >> 4;
                cp16(r1b_ + r1a(kb, row), &mv[(size_t)(m0 + row) * 4096 + kt + kb * 4]);
            }
#pragma unroll
            for (int i = 0; i < 16; i++) {
                int v = tid + i * 512;
                int kl = v >> 6, n = v & 63;
                cp4(sb + 131072 + ((kl >> 2) * 64 + n) * 16 + (kl & 3) * 4,
                    &Wm1[(size_t)kl * 4096 + kt + n]);
            }
            cp_commit();
        };
        auto issue_sub = [&](int o, int h) {
            uint32_t bbuf = sb + 163840 + h * 24576;
            int kt = o * 64 + h * 32;
#pragma unroll
            for (int i = 0; i < 12; i++) {
                int v = tid + i * 512;
                int kl = v / 192, n = v - kl * 192;
                const float* W = (n < 64) ? Wemv : (n < 128) ? Wzmv : Wamv;
                cp4(bbuf + ((kl >> 2) * 192 + n) * 16 + (kl & 3) * 4,
                    &W[(size_t)(kt + kl) * 64 + (n & 63)]);
            }
            cp_commit();
        };

        issue_mw(0);
#pragma unroll 1
        for (int o = 0; o < 64; o++) {
            cp_wait<0>();
            __syncthreads();                       // S1: mv/Wm1 visible; prior SIG done
            issue_sub(o, 0); issue_sub(o, 1);

            // gate mma: A = c0 (K=128), B = Wm1 slice (NB=64)
            float gacc[2][2][4];
#pragma unroll
            for (int mt = 0; mt < 2; mt++)
#pragma unroll
                for (int nt = 0; nt < 2; nt++)
#pragma unroll
                    for (int j = 0; j < 4; j++) gacc[mt][nt][j] = 0.f;
#pragma unroll
            for (int s = 0; s < 16; s++) {
                uint32_t a0[4], a1[4], b[4];
                ldsm4(a0, c0b + aoff0 + s * 4096);
                ldsm4(a1, c0b + aoff1 + s * 4096);
                ldsm4(b, sb + 131072 + gbo + s * 2048);
                mma8(gacc[0][0], a0, b[0], b[1]);
                mma8(gacc[0][1], a0, b[2], b[3]);
                mma8(gacc[1][0], a1, b[0], b[1]);
                mma8(gacc[1][1], a1, b[2], b[3]);
            }
            // epilogue: mempre = mv * sigmoid(gate + bm1) in place + direct STG.64
            const int kt = o * 64;
            const int r1o = 65536 + (o & 1) * 32768;
#pragma unroll
            for (int mt = 0; mt < 2; mt++)
#pragma unroll
                for (int nt = 0; nt < 2; nt++) {
                    int colb = wn * 16 + nt * 8 + fc2;
                    float b0v = __ldg(&bm1[kt + colb]);
                    float b1v = __ldg(&bm1[kt + colb + 1]);
                    int kb = colb >> 2, w0 = colb & 3;
#pragma unroll
                    for (int half = 0; half < 2; half++) {
                        int row = frow0 + mt * 16 + half * 8;
                        uint32_t off = r1o + r1a(kb, row) + w0 * 4;
                        float p0 = *(float*)(smem + off) *
                                   sigmoidf_(gacc[mt][nt][half * 2 + 0] + b0v);
                        float p1 = *(float*)(smem + off + 4) *
                                   sigmoidf_(gacc[mt][nt][half * 2 + 1] + b1v);
                        *(float*)(smem + off)     = p0;
                        *(float*)(smem + off + 4) = p1;
                        *(float2*)&g_mempre[(size_t)(m0 + row) * 4096 + kt + colb] =
                            make_float2(p0, p1);
                    }
                }
            __syncthreads();                       // S2: mempre visible; R2 free
            if (o < 63) { issue_mw(o + 1); cp_wait<1>(); }
            else        { cp_wait<0>(); }
            __syncthreads();                       // S3: Wsig subs visible

            // SIG mma: A = mempre block (K=64, swizzled), B = Wsig (NB=192)
            uint32_t r1b_ = sb + r1o;
#pragma unroll
            for (int h = 0; h < 2; h++) {
                uint32_t bbuf = sb + 163840 + h * 24576;
#pragma unroll
                for (int s = 0; s < 4; s++) {
                    int kb = 2 * (h * 4 + s) + (lane >> 4);
                    uint32_t ax = r1b_ +
                        (uint32_t)((kb * 128 + ((wm * 32 + (lane & 15)) ^ (kb & 7))) * 16);
                    uint32_t a0[4], a1[4];
                    ldsm4(a0, ax);
                    ldsm4(a1, ax + 256);
#pragma unroll
                    for (int p = 0; p < 3; p++) {
                        uint32_t b[4];
                        ldsm4(b, bbuf + boff4(192, wn, 48, p, lane) + s * 6144);
                        mma8(sacc[0][2 * p],     a0, b[0], b[1]);
                        mma8(sacc[0][2 * p + 1], a0, b[2], b[3]);
                        mma8(sacc[1][2 * p],     a1, b[0], b[1]);
                        mma8(sacc[1][2 * p + 1], a1, b[2], b[3]);
                    }
                }
            }
        }
    }

    // ============ P4a: sig dump + EZ = c0 @ [We|Wz] ============
    __syncthreads();
    {
        auto issue_ez = [&](const float* W) {
#pragma unroll
            for (int i = 0; i < 16; i++) {
                int v = tid + i * 512;
                int kl = v >> 6, n = v & 63;
                cp4(sb + 163840 + ((kl >> 2) * 64 + n) * 16 + (kl & 3) * 4,
                    &W[(size_t)kl * 64 + n]);
            }
            cp_commit();
        };
        issue_ez(We);
        float* siga = (float*)(smem + 65536);
#pragma unroll
        for (int mt = 0; mt < 2; mt++)
#pragma unroll
            for (int nt = 0; nt < 6; nt++)
#pragma unroll
                for (int idx = 0; idx < 4; idx++) {
                    int row = frow0 + mt * 16 + (idx >> 1) * 8;
                    int col = wn * 48 + nt * 8 + fc2 + (idx & 1);
                    float bv = (col < 64) ? __ldg(&bemv[col])
                             : (col < 128) ? __ldg(&bzmv[col - 64])
                                           : __ldg(&bamv[col - 128]);
                    siga[row * 192 + col] = sacc[mt][nt][idx] + bv;
                }
        cp_wait<0>(); __syncthreads();

        float eacc[2][2][4], zacc[2][2][4];
#pragma unroll
        for (int mt = 0; mt < 2; mt++)
#pragma unroll
            for (int nt = 0; nt < 2; nt++)
#pragma unroll
                for (int j = 0; j < 4; j++) { eacc[mt][nt][j] = 0.f; zacc[mt][nt][j] = 0.f; }
#pragma unroll
        for (int s = 0; s < 16; s++) {
            uint32_t a0[4], a1[4], b[4];
            ldsm4(a0, c0b + aoff0 + s * 4096);
            ldsm4(a1, c0b + aoff1 + s * 4096);
            ldsm4(b, sb + 163840 + gbo + s * 2048);
            mma8(eacc[0][0], a0, b[0], b[1]);
            mma8(eacc[0][1], a0, b[2], b[3]);
            mma8(eacc[1][0], a1, b[0], b[1]);
            mma8(eacc[1][1], a1, b[2], b[3]);
        }
        __syncthreads();
        issue_ez(Wz);
        cp_wait<0>(); __syncthreads();
#pragma unroll
        for (int s = 0; s < 16; s++) {
            uint32_t a0[4], a1[4], b[4];
            ldsm4(a0, c0b + aoff0 + s * 4096);
            ldsm4(a1, c0b + aoff1 + s * 4096);
            ldsm4(b, sb + 163840 + gbo + s * 2048);
            mma8(zacc[0][0], a0, b[0], b[1]);
            mma8(zacc[0][1], a0, b[2], b[3]);
            mma8(zacc[1][0], a1, b[0], b[1]);
            mma8(zacc[1][1], a1, b[2], b[3]);
        }
        __syncthreads();  // c0 reads complete before overwrite
        float* e1a = (float*)smem;
        float* z1a = (float*)(smem + 32768);
#pragma unroll
        for (int mt = 0; mt < 2; mt++)
#pragma unroll
            for (int nt = 0; nt < 2; nt++)
#pragma unroll
                for (int idx = 0; idx < 4; idx++) {
                    int row = frow0 + mt * 16 + (idx >> 1) * 8;
                    int col = wn * 16 + nt * 8 + fc2 + (idx & 1);
                    e1a[row * 64 + col] = sigmoidf_(eacc[mt][nt][idx] + __ldg(&be[col]));
                    z1a[row * 64 + col] = zacc[mt][nt][idx] + __ldg(&bz[col]);
                }
        __syncthreads();
    }

    // ============ P4b: zt, erase, add ============
    {
        float* e1a  = (float*)smem;
        float* z1a  = (float*)(smem + 32768);
        float* siga = (float*)(smem + 65536);

        float zaacc[2][2][4];
#pragma unroll
        for (int mt = 0; mt < 2; mt++)
#pragma unroll
            for (int nt = 0; nt < 2; nt++)
#pragma unroll
                for (int j = 0; j < 4; j++) zaacc[mt][nt][j] = 0.f;

#pragma unroll 1
        for (int h = 0; h < 2; h++) {
#pragma unroll
            for (int i = 0; i < 4; i++) {
                int v = tid + i * 512;
                int kl = v >> 6, n = v & 63;
                cp4(sb + 180224 + ((kl >> 2) * 64 + n) * 16 + (kl & 3) * 4,
                    &Wza[(size_t)(h * 32 + kl) * 64 + n]);
            }
            cp_commit();
#pragma unroll
            for (int i = 0; i < 8; i++) {
                int v = tid + i * 512;
                int row = v >> 5, jl = v & 31;
                int j = h * 32 + jl;
                float ztv = sigmoidf_(z1a[row * 64 + j] + siga[row * 192 + 64 + j]);
                *(float*)(smem + 163840 + ((jl >> 2) * 128 + row) * 16 + (jl & 3) * 4) = ztv;
                e1a[row * 64 + j] = sigmoidf_(e1a[row * 64 + j] + sigmoidf_(siga[row * 192 + j]));
            }
            cp_wait<0>(); __syncthreads();
#pragma unroll
            for (int s = 0; s < 4; s++) {
                uint32_t a0[4], a1[4], b[4];
                ldsm4(a0, sb + 163840 + aoff0 + s * 4096);
                ldsm4(a1, sb + 163840 + aoff1 + s * 4096);
                ldsm4(b, sb + 180224 + gbo + s * 2048);
                mma8(zaacc[0][0], a0, b[0], b[1]);
                mma8(zaacc[0][1], a0, b[2], b[3]);
                mma8(zaacc[1][0], a1, b[0], b[1]);
                mma8(zaacc[1][1], a1, b[2], b[3]);
            }
            __syncthreads();
        }
#pragma unroll
        for (int mt = 0; mt < 2; mt++)
#pragma unroll
            for (int nt = 0; nt < 2; nt++)
#pragma unroll
                for (int idx = 0; idx < 4; idx++) {
                    int row = frow0 + mt * 16 + (idx >> 1) * 8;
                    int col = wn * 16 + nt * 8 + fc2 + (idx & 1);
                    z1a[row * 64 + col] =
                        tanhf(tanhf(zaacc[mt][nt][idx] + __ldg(&bza[col])) +
                              tanhf(siga[row * 192 + 128 + col]));
                }
        __syncthreads();
#pragma unroll
        for (int i = 0; i < 4; i++) {
            int v = tid + i * 512;
            *(float4*)(smem + 188416 + v * 16) = *(const float4*)&g_ww[(size_t)m0 * 64 + v * 4];
        }
        __syncthreads();
    }

    // ============ P5: out = mempre*(1 - w*erase) + w*add ============
    {
        const float* er = (const float*)smem;
        const float* ad = (const float*)(smem + 32768);
        const float* sw = (const float*)(smem + 188416);
#pragma unroll 4
        for (int it = 0; it < 256; it++) {
            int v = tid + it * 512;
            int row = v >> 10, q = v & 1023;
            float4 mp = *(const float4*)&g_mempre[(size_t)(m0 + row) * 4096 + q * 4];
            float w = sw[row * 64 + (q >> 4)];
            float4 e4 = *(const float4*)&er[row * 64 + (q & 15) * 4];
            float4 a4 = *(const float4*)&ad[row * 64 + (q & 15) * 4];
            float4 r;
            r.x = mp.x * (1.f - w * e4.x) + w * a4.x;
            r.y = mp.y * (1.f - w * e4.y) + w * a4.y;
            r.z = mp.z * (1.f - w * e4.z) + w * a4.z;
            r.w = mp.w * (1.f - w * e4.w) + w * a4.w;
            *(float4*)&outp[(size_t)(m0 + row) * 4096 + q * 4] = r;
        }
    }
}

// ---------------- write_weight: softmax(control_key @ memory_key^T) ----------------
__global__ void __launch_bounds__(256) ww_k(const float* __restrict__ ck,
                                            const float* __restrict__ mk)
{
    int g = threadIdx.x >> 6;
    int t = threadIdx.x & 63;
    int b = blockIdx.x * 4 + g;
    __shared__ float sck[4][64];
    __shared__ float pmax[4][2];
    __shared__ float psum[4][2];

    sck[g][t] = ck[b * 64 + t];
    __syncthreads();
    float dot = 0.f;
#pragma unroll 8
    for (int k = 0; k < 64; k++) dot = fmaf(sck[g][k], mk[t * 64 + k], dot);

    float mx = dot;
#pragma unroll
    for (int o = 16; o > 0; o >>= 1) mx = fmaxf(mx, __shfl_xor_sync(0xffffffffu, mx, o));
    int wl = t >> 5;
    if ((t & 31) == 0) pmax[g][wl] = mx;
    __syncthreads();
    mx = fmaxf(pmax[g][0], pmax[g][1]);

    float e = __expf(dot - mx);
    float s = e;
#pragma unroll
    for (int o = 16; o > 0; o >>= 1) s += __shfl_xor_sync(0xffffffffu, s, o);
    if ((t & 31) == 0) psum[g][wl] = s;
    __syncthreads();
    s = psum[g][0] + psum[g][1];

    g_ww[b * 64 + t] = e / s;
}

// ====================== launch ======================
extern "C" void kernel_launch(void* const* d_in, const int* in_sizes, int n_in,
                              void* d_out, int out_size)
{
    const float* control_key  = (const float*)d_in[0];
    const float* control_qa   = (const float*)d_in[1];
    const float* memory_key   = (const float*)d_in[2];
    const float* memory_value = (const float*)d_in[3];
    const float* We   = (const float*)d_in[4];
    const float* be   = (const float*)d_in[5];
    const float* Wemv = (const float*)d_in[6];
    const float* bemv = (const float*)d_in[7];
    const float* Wza  = (const float*)d_in[8];
    const float* bza  = (const float*)d_in[9];
    const float* Wamv = (const float*)d_in[10];
    const float* bamv = (const float*)d_in[11];
    const float* Wc0  = (const float*)d_in[12];
    const float* bc0  = (const float*)d_in[13];
    const float* Wm1  = (const float*)d_in[14];
    const float* bm1  = (const float*)d_in[15];
    const float* Wz   = (const float*)d_in[16];
    const float* bz   = (const float*)d_in[17];
    const float* Wzmv = (const float*)d_in[18];
    const float* bzmv = (const float*)d_in[19];
    float* out = (float*)d_out;

    cudaFuncSetAttribute(fused_k, cudaFuncAttributeMaxDynamicSharedMemorySize, SMEM_TOTAL);

    ww_k<<<BB / 4, 256>>>(control_key, memory_key);

    fused_k<<<BB / 128, 512, SMEM_TOTAL>>>(
        control_qa, memory_value,
        We, be, Wemv, bemv, Wza, bza, Wamv, bamv,
        Wc0, bc0, Wm1, bm1, Wz, bz, Wzmv, bzmv,
        out);
}